// round 14
// baseline (speedup 1.0000x reference)
#include <cuda_runtime.h>
#include <cuda_bf16.h>
#include <cuda_fp8.h>
#include <cstdint>

#define BATCH 4096
#define NVIEW 2
#define DIM   512
#define NTOT  8192
#define NCLS  1000

#define C_EXP  20.60992915555662f   // log2(e)/0.07
#define INV_T  14.285714285714286f  // 1/0.07
#define EBIAS  10.0f
#define ESCALE 1024.0f              // 2^EBIAS

#define NTILES_TOTAL 2080
#define NCTA 148

// ---------------- smem layout (bytes) ----------------
#define A_STRIDE   528                 // 512 fp8 + 16 pad per row -> conflict-free ldmatrix
#define A_BYTES    (128 * A_STRIDE)    // 67584
#define B_STRIDE   272                 // 256 fp8 + 16 pad
#define B_STAGE    (128 * B_STRIDE)    // 34816
#define OFF_A      0
#define OFF_B      A_BYTES
#define OFF_RED    (OFF_B + 3 * B_STAGE)      // 172032
#define OFF_MBAR   (OFF_RED + 4 * 128 * 4)    // 174080  full[3]@0,8,16  empty[3]@24,32,40
#define SMEM_TOTAL (OFF_MBAR + 48)            // 174128

// ---------------- scratch ----------------
__device__ __align__(16) __nv_bfloat16 g_A[(size_t)NTOT * DIM];
__device__ __align__(16) uint8_t       g_A8[(size_t)NTOT * DIM];
__device__ __align__(16) float         g_Ssum[NCLS * DIM];
__device__ float g_Z[NTOT];
__device__ float g_sum;
__device__ int   g_cnt[NCLS];
__device__ unsigned g_done;

// ---------------- PTX helpers ----------------
__device__ __forceinline__ void ldm4(uint32_t r[4], uint32_t addr) {
    asm volatile("ldmatrix.sync.aligned.m8n8.x4.shared.b16 {%0,%1,%2,%3}, [%4];"
        : "=r"(r[0]), "=r"(r[1]), "=r"(r[2]), "=r"(r[3]) : "r"(addr));
}
__device__ __forceinline__ void qmma(float c[4], const uint32_t a[4], const uint32_t b[2]) {
    asm volatile("mma.sync.aligned.m16n8k32.row.col.f32.e4m3.e4m3.f32 "
        "{%0,%1,%2,%3}, {%4,%5,%6,%7}, {%8,%9}, {%0,%1,%2,%3};"
        : "+f"(c[0]), "+f"(c[1]), "+f"(c[2]), "+f"(c[3])
        : "r"(a[0]), "r"(a[1]), "r"(a[2]), "r"(a[3]), "r"(b[0]), "r"(b[1]));
}
__device__ __forceinline__ uint32_t smem_u32(const void* p) {
    uint32_t a;
    asm("{ .reg .u64 t; cvta.to.shared.u64 t, %1; cvt.u32.u64 %0, t; }" : "=r"(a) : "l"(p));
    return a;
}
__device__ __forceinline__ void bulk_cp(uint32_t dst, const void* src, uint32_t bytes, uint32_t mbar) {
    asm volatile("cp.async.bulk.shared::cta.global.mbarrier::complete_tx::bytes [%0], [%1], %2, [%3];"
        :: "r"(dst), "l"(src), "r"(bytes), "r"(mbar) : "memory");
}
__device__ __forceinline__ void bulk_red_add_f32(void* gdst, uint32_t ssrc, uint32_t bytes) {
    asm volatile("cp.reduce.async.bulk.global.shared::cta.bulk_group.add.f32 [%0], [%1], %2;"
        :: "l"(gdst), "r"(ssrc), "r"(bytes) : "memory");
}
__device__ __forceinline__ void bulk_commit() {
    asm volatile("cp.async.bulk.commit_group;" ::: "memory");
}
__device__ __forceinline__ void bulk_wait0() {
    asm volatile("cp.async.bulk.wait_group 0;" ::: "memory");
}
__device__ __forceinline__ void mbar_init(uint32_t mbar, uint32_t cnt) {
    asm volatile("mbarrier.init.shared.b64 [%0], %1;" :: "r"(mbar), "r"(cnt) : "memory");
}
__device__ __forceinline__ void mbar_expect(uint32_t mbar, uint32_t bytes) {
    asm volatile("mbarrier.arrive.expect_tx.shared.b64 _, [%0], %1;" :: "r"(mbar), "r"(bytes) : "memory");
}
__device__ __forceinline__ void mbar_arrive(uint32_t mbar) {
    asm volatile("mbarrier.arrive.release.cta.shared.b64 _, [%0];" :: "r"(mbar) : "memory");
}
__device__ __forceinline__ void mbar_wait(uint32_t mbar, uint32_t parity) {
    uint32_t done;
    asm volatile("{ .reg .pred p; mbarrier.try_wait.parity.acquire.cta.shared::cta.b64 p, [%1], %2; selp.b32 %0, 1, 0, p; }"
        : "=r"(done) : "r"(mbar), "r"(parity) : "memory");
    if (!done) {
        asm volatile("{ .reg .pred P1;\n"
            "W_%=: mbarrier.try_wait.parity.acquire.cta.shared::cta.b64 P1, [%0], %1, 0x989680;\n"
            "@P1 bra.uni D_%=;\n bra.uni W_%=;\n D_%=: }"
            :: "r"(mbar), "r"(parity) : "memory");
    }
}
__device__ __forceinline__ void named_bar(int id, int nthreads) {
    asm volatile("bar.sync %0, %1;" :: "r"(id), "r"(nthreads) : "memory");
}
__device__ __forceinline__ uint32_t pack_h2(float lo, float hi) {
    uint32_t h;
    asm("cvt.rn.f16x2.f32 %0, %1, %2;" : "=r"(h) : "f"(hi), "f"(lo));
    return h;
}
__device__ __forceinline__ uint32_t ex2_h2(uint32_t x) {
    uint32_t e;
    asm("ex2.approx.f16x2 %0, %1;" : "=r"(e) : "r"(x));
    return e;
}
__device__ __forceinline__ uint32_t hadd2(uint32_t a, uint32_t b) {
    uint32_t d;
    asm("add.rn.f16x2 %0, %1, %2;" : "=r"(d) : "r"(a), "r"(b));
    return d;
}
__device__ __forceinline__ float2 h2_to_f2(uint32_t h) {
    float lo, hi;
    asm("{ .reg .f16 l, hh; mov.b32 {l, hh}, %2; cvt.f32.f16 %0, l; cvt.f32.f16 %1, hh; }"
        : "=f"(lo), "=f"(hi) : "r"(h));
    return make_float2(lo, hi);
}
// flattened upper-triangle tile list: iblk<32 -> c in [0,33), else c in [0,32)
__device__ __forceinline__ void decode_tile(int g, int& ib, int& c) {
    if (g < 1056) { ib = g / 33; c = g - ib * 33; }
    else { int h = g - 1056; ib = 32 + (h >> 5); c = h & 31; }
}

// ------------------------- kernel 1: normalize + view-swap + bulk-reduce class sums -------------------------
__global__ void norm_kernel(const float* __restrict__ feats, const int* __restrict__ labels) {
    __shared__ float stage[8][DIM];
    int warp = threadIdx.x >> 5, lane = threadIdx.x & 31;
    int row  = blockIdx.x * 8 + warp;
    int b = row & (BATCH - 1);
    int v = row >> 12;
    const int cls = labels[b];
    const float4* src = reinterpret_cast<const float4*>(feats + (size_t)(b * NVIEW + v) * DIM);
    float4 f[4];
    float ss = 0.f;
#pragma unroll
    for (int q = 0; q < 4; q++) {
        f[q] = src[lane + 32 * q];
        ss += f[q].x * f[q].x + f[q].y * f[q].y + f[q].z * f[q].z + f[q].w * f[q].w;
    }
#pragma unroll
    for (int o = 16; o; o >>= 1) ss += __shfl_xor_sync(0xffffffffu, ss, o);
    float sc = 1.0f / fmaxf(sqrtf(ss), 1e-8f);
    if (lane == 0) {
        g_Z[row] = 0.f;
        if (v == 0) atomicAdd(&g_cnt[cls], 1);
    }
    uint2* dst = reinterpret_cast<uint2*>(g_A + (size_t)row * DIM);
    uint32_t* dst8 = reinterpret_cast<uint32_t*>(g_A8 + (size_t)row * DIM);
    float4* srow = reinterpret_cast<float4*>(stage[warp]);
#pragma unroll
    for (int q = 0; q < 4; q++) {
        float x = f[q].x * sc, y = f[q].y * sc, z = f[q].z * sc, w = f[q].w * sc;
        __nv_bfloat162 p0 = __floats2bfloat162_rn(x, y);
        __nv_bfloat162 p1 = __floats2bfloat162_rn(z, w);
        uint2 pk;
        pk.x = *reinterpret_cast<uint32_t*>(&p0);
        pk.y = *reinterpret_cast<uint32_t*>(&p1);
        dst[lane + 32 * q] = pk;
        __nv_fp8x2_storage_t lo = __nv_cvt_float2_to_fp8x2(make_float2(x, y), __NV_SATFINITE, __NV_E4M3);
        __nv_fp8x2_storage_t hi = __nv_cvt_float2_to_fp8x2(make_float2(z, w), __NV_SATFINITE, __NV_E4M3);
        dst8[lane + 32 * q] = (uint32_t)lo | ((uint32_t)hi << 16);
        srow[lane + 32 * q] = make_float4(x, y, z, w);
    }
    asm volatile("fence.proxy.async.shared::cta;" ::: "memory");
    __syncwarp();
    if (lane == 0) {
        bulk_red_add_f32(g_Ssum + (size_t)cls * DIM, smem_u32(stage[warp]), DIM * 4);
        bulk_commit();
        bulk_wait0();
    }
}

// ------------------------- kernel 2: fp8 GEMM, dedicated-producer 3-stage ring -------------------------
__global__ void __launch_bounds__(544, 1) supcon_main() {
    extern __shared__ char smem[];
    const int t = threadIdx.x, lane = t & 31, wid = t >> 5;
    const int g0 = (NTILES_TOTAL * blockIdx.x) / NCTA;
    const int g1 = (NTILES_TOTAL * (blockIdx.x + 1)) / NCTA;
    const int NCHUNK = 2 * (g1 - g0);
    const uint32_t sbase = smem_u32(smem);
    const uint32_t mbf = sbase + OFF_MBAR;        // full[3]
    const uint32_t mbe = sbase + OFF_MBAR + 24;   // empty[3]
    float* red = reinterpret_cast<float*>(smem + OFF_RED);   // [4][128]

    if (t == 0) {
#pragma unroll
        for (int s = 0; s < 3; s++) { mbar_init(mbf + s * 8, 1); mbar_init(mbe + s * 8, 16); }
    }

    int ib0, c0;
    decode_tile(g0, ib0, c0);

    // consumers load initial A tile
    if (wid < 16) {
        for (int f = t; f < 4096; f += 512) {
            int row = f >> 5, seg = f & 31;
            uint4 v = *reinterpret_cast<const uint4*>(g_A8 + (size_t)(ib0 * 128 + row) * DIM + seg * 16);
            *reinterpret_cast<uint4*>(smem + OFF_A + row * A_STRIDE + seg * 16) = v;
        }
    }
    __syncthreads();   // A visible + mbars initialized (whole block, once)

    if (wid == 16) {
        // ================= producer warp =================
        for (int nc = 0; nc < NCHUNK; nc++) {
            const int s = nc % 3;
            if (nc >= 3) mbar_wait(mbe + s * 8, (uint32_t)((nc - 3) / 3) & 1u);
            int ib, c;
            decode_tile(g0 + (nc >> 1), ib, c);
            const uint8_t* src = g_A8 + (size_t)((ib + c) & 63) * (128 * DIM) + (nc & 1) * 256;
            if (lane == 0) mbar_expect(mbf + s * 8, 32768);
            __syncwarp();
#pragma unroll
            for (int r = 0; r < 4; r++) {
                const int row = lane * 4 + r;
                bulk_cp(sbase + OFF_B + s * B_STAGE + row * B_STRIDE,
                        src + (size_t)row * DIM, 256, mbf + s * 8);
            }
        }
    } else {
        // ================= 16 consumer warps =================
        const int warp_m = wid >> 2, warp_n = wid & 3;      // 4 x 4 warps, 32x32 tiles
        const uint32_t abase = sbase + OFF_A + (warp_m * 32 + (lane & 15)) * A_STRIDE + (lane >> 4) * 16;
        const uint32_t bb_lane = (((lane & 7) + ((lane >> 4) & 1) * 8) + warp_n * 32) * B_STRIDE + ((lane >> 3) & 1) * 16;

        float acc[2][4][4];
#pragma unroll
        for (int m = 0; m < 2; m++)
#pragma unroll
            for (int n = 0; n < 4; n++)
#pragma unroll
                for (int r = 0; r < 4; r++) acc[m][n][r] = 0.f;
        float z[4] = {0.f, 0.f, 0.f, 0.f};
        int cur_ib = ib0;

        for (int cc = 0; cc < NCHUNK; cc++) {
            int ib, c;
            decode_tile(g0 + (cc >> 1), ib, c);
            if (ib != cur_ib) {              // only at even cc (tile start)
                // flush row sums for cur_ib (consumer-only named barrier)
#pragma unroll
                for (int q = 0; q < 4; q++) {
                    z[q] += __shfl_xor_sync(0xffffffffu, z[q], 1);
                    z[q] += __shfl_xor_sync(0xffffffffu, z[q], 2);
                }
                named_bar(1, 512);
                if ((lane & 3) == 0) {
                    int g4 = lane >> 2;
#pragma unroll
                    for (int m = 0; m < 2; m++)
#pragma unroll
                        for (int h = 0; h < 2; h++)
                            red[warp_n * 128 + warp_m * 32 + m * 16 + h * 8 + g4] = z[2 * m + h];
                }
                named_bar(1, 512);
                if (t < 128)
                    atomicAdd(&g_Z[cur_ib * 128 + t],
                              (red[t] + red[128 + t] + red[256 + t] + red[384 + t]) * ESCALE);
                z[0] = z[1] = z[2] = z[3] = 0.f;
                // reload A for new iblk (all consumers past MMA of old A)
                for (int f = t; f < 4096; f += 512) {
                    int row = f >> 5, seg = f & 31;
                    uint4 v = *reinterpret_cast<const uint4*>(g_A8 + (size_t)(ib * 128 + row) * DIM + seg * 16);
                    *reinterpret_cast<uint4*>(smem + OFF_A + row * A_STRIDE + seg * 16) = v;
                }
                cur_ib = ib;
                named_bar(1, 512);
            }

            const int s = cc % 3;
            mbar_wait(mbf + s * 8, (uint32_t)(cc / 3) & 1u);

            const uint32_t bb = sbase + OFF_B + s * B_STAGE + bb_lane;
            const int ch = cc & 1;
#pragma unroll
            for (int ks = 0; ks < 8; ks++) {
                const int koff = ks * 32;
                uint32_t a[2][4];
                ldm4(a[0], abase + (ch * 256 + koff));
                ldm4(a[1], abase + 16 * A_STRIDE + (ch * 256 + koff));
                uint32_t b[4][2];
#pragma unroll
                for (int p = 0; p < 2; p++) {
                    uint32_t r4[4];
                    ldm4(r4, bb + p * (16 * B_STRIDE) + koff);
                    b[2 * p][0] = r4[0]; b[2 * p][1] = r4[1];
                    b[2 * p + 1][0] = r4[2]; b[2 * p + 1][1] = r4[3];
                }
#pragma unroll
                for (int m = 0; m < 2; m++)
#pragma unroll
                    for (int n = 0; n < 4; n++) qmma(acc[m][n], a[m], b[n]);
            }
            if (lane == 0) mbar_arrive(mbe + s * 8);   // free slot before epilogue

            if (ch) {   // tile complete -> register-only epilogue
                const int jblk = (ib + c) & 63;
                const bool dg = (c == 0);
                uint32_t zh[4] = {0, 0, 0, 0};
                uint32_t csh[4] = {0, 0, 0, 0};
#pragma unroll
                for (int m = 0; m < 2; m++)
#pragma unroll
                    for (int n = 0; n < 4; n++)
#pragma unroll
                        for (int h = 0; h < 2; h++) {
                            float x0 = acc[m][n][2 * h]     * C_EXP - EBIAS;
                            float x1 = acc[m][n][2 * h + 1] * C_EXP - EBIAS;
                            if (dg) {
                                int rl = warp_m * 32 + m * 16 + h * 8 + (lane >> 2);
                                int cl0 = warp_n * 32 + n * 8 + (lane & 3) * 2;
                                if (rl == cl0)     x0 = -60.f;
                                if (rl == cl0 + 1) x1 = -60.f;
                            }
                            uint32_t e2 = ex2_h2(pack_h2(x0, x1));
                            zh[2 * m + h] = hadd2(zh[2 * m + h], e2);
                            csh[n] = hadd2(csh[n], e2);
                            acc[m][n][2 * h] = 0.f; acc[m][n][2 * h + 1] = 0.f;
                        }
#pragma unroll
                for (int q = 0; q < 4; q++) {
                    float2 f = h2_to_f2(zh[q]);
                    z[q] += f.x + f.y;
                }
                if (!dg) {
#pragma unroll
                    for (int n = 0; n < 4; n++) {
                        uint32_t v = csh[n];
                        v = hadd2(v, __shfl_xor_sync(0xffffffffu, v, 4));
                        v = hadd2(v, __shfl_xor_sync(0xffffffffu, v, 8));
                        v = hadd2(v, __shfl_xor_sync(0xffffffffu, v, 16));
                        csh[n] = v;
                    }
                    if (lane < 4) {
                        float* zj = &g_Z[jblk * 128 + warp_n * 32 + lane * 2];
#pragma unroll
                        for (int n = 0; n < 4; n++) {
                            float2 f = h2_to_f2(csh[n]);
                            atomicAdd(&zj[n * 8 + 0], f.x * ESCALE);
                            atomicAdd(&zj[n * 8 + 1], f.y * ESCALE);
                        }
                    }
                }
            }
        }

        // final flush of row sums for cur_ib
#pragma unroll
        for (int q = 0; q < 4; q++) {
            z[q] += __shfl_xor_sync(0xffffffffu, z[q], 1);
            z[q] += __shfl_xor_sync(0xffffffffu, z[q], 2);
        }
        named_bar(1, 512);
        if ((lane & 3) == 0) {
            int g4 = lane >> 2;
#pragma unroll
            for (int m = 0; m < 2; m++)
#pragma unroll
                for (int h = 0; h < 2; h++)
                    red[warp_n * 128 + warp_m * 32 + m * 16 + h * 8 + g4] = z[2 * m + h];
        }
        named_bar(1, 512);
        if (t < 128)
            atomicAdd(&g_Z[cur_ib * 128 + t],
                      (red[t] + red[128 + t] + red[256 + t] + red[384 + t]) * ESCALE);
    }
}

// ------------------------- kernel 3: per-row loss + last-block final write -------------------------
__global__ void finalize1(const int* __restrict__ labels, float* __restrict__ out) {
    __shared__ float wsum[8];
    const int t = threadIdx.x, lane = t & 31, wid = t >> 5;
    const int row = blockIdx.x * 8 + wid;
    const int b = row & (BATCH - 1);
    const int cls = labels[b];
    const uint2* arow = reinterpret_cast<const uint2*>(g_A) + (size_t)row * 128;
    const float4* srow = reinterpret_cast<const float4*>(g_Ssum) + (size_t)cls * 128;
    float dot = 0.f, self = 0.f;
#pragma unroll
    for (int q = 0; q < 4; q++) {
        uint2 u = arow[lane + 32 * q];
        float4 s = srow[lane + 32 * q];
        float2 a0 = __bfloat1622float2(*reinterpret_cast<const __nv_bfloat162*>(&u.x));
        float2 a1 = __bfloat1622float2(*reinterpret_cast<const __nv_bfloat162*>(&u.y));
        dot  += a0.x * s.x + a0.y * s.y + a1.x * s.z + a1.y * s.w;
        self += a0.x * a0.x + a0.y * a0.y + a1.x * a1.x + a1.y * a1.y;
    }
#pragma unroll
    for (int o = 16; o; o >>= 1) {
        dot  += __shfl_xor_sync(0xffffffffu, dot, o);
        self += __shfl_xor_sync(0xffffffffu, self, o);
    }
    if (lane == 0) {
        float C = 2.0f * (float)g_cnt[cls] - 1.0f;
        float Z = g_Z[row];
        float S = (dot - self) * INV_T;
        wsum[wid] = (S - C * logf(Z + 1e-8f)) / (C + 1e-8f);
    }
    __syncthreads();
    if (t == 0) {
        float bs = 0.f;
#pragma unroll
        for (int w = 0; w < 8; w++) bs += wsum[w];
        atomicAdd(&g_sum, bs);
        __threadfence();
        unsigned tk = atomicAdd(&g_done, 1u);
        if (tk == gridDim.x - 1) {
            float s;
            asm volatile("ld.acquire.gpu.f32 %0, [%1];" : "=f"(s) : "l"(&g_sum));
            out[0] = -s / (float)NTOT;
        }
    }
}

// ------------------------- launch -------------------------
extern "C" void kernel_launch(void* const* d_in, const int* in_sizes, int n_in,
                              void* d_out, int out_size) {
    const float* feats = (const float*)d_in[0];
    const int* labels = (const int*)d_in[1];
    (void)in_sizes; (void)n_in; (void)out_size;

    void* p_ssum = nullptr; void* p_cnt = nullptr; void* p_sum = nullptr; void* p_done = nullptr;
    cudaGetSymbolAddress(&p_ssum, g_Ssum);
    cudaGetSymbolAddress(&p_cnt, g_cnt);
    cudaGetSymbolAddress(&p_sum, g_sum);
    cudaGetSymbolAddress(&p_done, g_done);
    cudaMemsetAsync(p_ssum, 0, (size_t)NCLS * DIM * sizeof(float));
    cudaMemsetAsync(p_cnt, 0, NCLS * sizeof(int));
    cudaMemsetAsync(p_sum, 0, sizeof(float));
    cudaMemsetAsync(p_done, 0, sizeof(unsigned));

    cudaFuncSetAttribute(supcon_main, cudaFuncAttributeMaxDynamicSharedMemorySize, SMEM_TOTAL);

    norm_kernel<<<NTOT / 8, 256>>>(feats, labels);
    supcon_main<<<NCTA, 544, SMEM_TOTAL>>>();
    finalize1<<<NTOT / 8, 256>>>(labels, (float*)d_out);
}

// round 15
// speedup vs baseline: 1.3878x; 1.3878x over previous
#include <cuda_runtime.h>
#include <cuda_bf16.h>
#include <cuda_fp8.h>
#include <cstdint>

#define BATCH 4096
#define NVIEW 2
#define DIM   512
#define NTOT  8192
#define NCLS  1000

#define C_EXP  20.60992915555662f   // log2(e)/0.07
#define INV_T  14.285714285714286f  // 1/0.07
#define EBIAS  10.0f
#define ESCALE 1024.0f              // 2^EBIAS

#define NTILES_TOTAL 2080
#define NCTA 148

// ---------------- smem layout (bytes) ----------------
#define A_STRIDE   528                 // 512 fp8 + 16 pad per row -> conflict-free ldmatrix
#define TILE_BYTES (128 * A_STRIDE)    // 67584
#define OFF_A      0
#define OFF_B      TILE_BYTES          // two full-K B stages
#define OFF_RED    (OFF_B + 2 * TILE_BYTES)   // 202752
#define OFF_MBAR   (OFF_RED + 4 * 128 * 4)    // 204800
#define SMEM_TOTAL (OFF_MBAR + 16)            // 204816

// ---------------- scratch ----------------
__device__ __align__(16) __nv_bfloat16 g_A[(size_t)NTOT * DIM];
__device__ __align__(16) uint8_t       g_A8[(size_t)NTOT * DIM];
__device__ __align__(16) float         g_Ssum[NCLS * DIM];
__device__ float g_Z[NTOT];
__device__ float g_sum;
__device__ int   g_cnt[NCLS];
__device__ unsigned g_done;

// ---------------- PTX helpers ----------------
__device__ __forceinline__ void ldm4(uint32_t r[4], uint32_t addr) {
    asm volatile("ldmatrix.sync.aligned.m8n8.x4.shared.b16 {%0,%1,%2,%3}, [%4];"
        : "=r"(r[0]), "=r"(r[1]), "=r"(r[2]), "=r"(r[3]) : "r"(addr));
}
__device__ __forceinline__ void qmma(float c[4], const uint32_t a[4], const uint32_t b[2]) {
    asm volatile("mma.sync.aligned.m16n8k32.row.col.f32.e4m3.e4m3.f32 "
        "{%0,%1,%2,%3}, {%4,%5,%6,%7}, {%8,%9}, {%0,%1,%2,%3};"
        : "+f"(c[0]), "+f"(c[1]), "+f"(c[2]), "+f"(c[3])
        : "r"(a[0]), "r"(a[1]), "r"(a[2]), "r"(a[3]), "r"(b[0]), "r"(b[1]));
}
__device__ __forceinline__ uint32_t smem_u32(const void* p) {
    uint32_t a;
    asm("{ .reg .u64 t; cvta.to.shared.u64 t, %1; cvt.u32.u64 %0, t; }" : "=r"(a) : "l"(p));
    return a;
}
__device__ __forceinline__ void bulk_cp(uint32_t dst, const void* src, uint32_t bytes, uint32_t mbar) {
    asm volatile("cp.async.bulk.shared::cta.global.mbarrier::complete_tx::bytes [%0], [%1], %2, [%3];"
        :: "r"(dst), "l"(src), "r"(bytes), "r"(mbar) : "memory");
}
__device__ __forceinline__ void bulk_red_add_f32(void* gdst, uint32_t ssrc, uint32_t bytes) {
    asm volatile("cp.reduce.async.bulk.global.shared::cta.bulk_group.add.f32 [%0], [%1], %2;"
        :: "l"(gdst), "r"(ssrc), "r"(bytes) : "memory");
}
__device__ __forceinline__ void bulk_commit() {
    asm volatile("cp.async.bulk.commit_group;" ::: "memory");
}
__device__ __forceinline__ void bulk_wait0() {
    asm volatile("cp.async.bulk.wait_group 0;" ::: "memory");
}
__device__ __forceinline__ void mbar_init(uint32_t mbar, uint32_t cnt) {
    asm volatile("mbarrier.init.shared.b64 [%0], %1;" :: "r"(mbar), "r"(cnt) : "memory");
}
__device__ __forceinline__ void mbar_expect(uint32_t mbar, uint32_t bytes) {
    asm volatile("mbarrier.arrive.expect_tx.shared.b64 _, [%0], %1;" :: "r"(mbar), "r"(bytes) : "memory");
}
__device__ __forceinline__ void mbar_wait(uint32_t mbar, uint32_t parity) {
    uint32_t done;
    asm volatile("{ .reg .pred p; mbarrier.try_wait.parity.acquire.cta.shared::cta.b64 p, [%1], %2; selp.b32 %0, 1, 0, p; }"
        : "=r"(done) : "r"(mbar), "r"(parity) : "memory");
    if (!done) {
        asm volatile("{ .reg .pred P1;\n"
            "W_%=: mbarrier.try_wait.parity.acquire.cta.shared::cta.b64 P1, [%0], %1, 0x989680;\n"
            "@P1 bra.uni D_%=;\n bra.uni W_%=;\n D_%=: }"
            :: "r"(mbar), "r"(parity) : "memory");
    }
}
__device__ __forceinline__ uint32_t pack_h2(float lo, float hi) {
    uint32_t h;
    asm("cvt.rn.f16x2.f32 %0, %1, %2;" : "=r"(h) : "f"(hi), "f"(lo));
    return h;
}
__device__ __forceinline__ uint32_t ex2_h2(uint32_t x) {
    uint32_t e;
    asm("ex2.approx.f16x2 %0, %1;" : "=r"(e) : "r"(x));
    return e;
}
__device__ __forceinline__ uint32_t hadd2(uint32_t a, uint32_t b) {
    uint32_t d;
    asm("add.rn.f16x2 %0, %1, %2;" : "=r"(d) : "r"(a), "r"(b));
    return d;
}
__device__ __forceinline__ float2 h2_to_f2(uint32_t h) {
    float lo, hi;
    asm("{ .reg .f16 l, hh; mov.b32 {l, hh}, %2; cvt.f32.f16 %0, l; cvt.f32.f16 %1, hh; }"
        : "=f"(lo), "=f"(hi) : "r"(h));
    return make_float2(lo, hi);
}
// flattened upper-triangle tile list: iblk<32 -> c in [0,33), else c in [0,32)
__device__ __forceinline__ void decode_tile(int g, int& ib, int& c) {
    if (g < 1056) { ib = g / 33; c = g - ib * 33; }
    else { int h = g - 1056; ib = 32 + (h >> 5); c = h & 31; }
}

// ------------------------- kernel 1: normalize both views per warp + one bulk-reduce per sample -------------------------
__global__ void norm_kernel(const float* __restrict__ feats, const int* __restrict__ labels) {
    __shared__ float stage[8][DIM];
    const int warp = threadIdx.x >> 5, lane = threadIdx.x & 31;
    const int b = blockIdx.x * 8 + warp;          // sample 0..4095
    const int cls = labels[b];
    const float4* src0 = reinterpret_cast<const float4*>(feats + (size_t)(b * NVIEW + 0) * DIM);
    const float4* src1 = reinterpret_cast<const float4*>(feats + (size_t)(b * NVIEW + 1) * DIM);
    float4 f0[4], f1[4];
    float ss0 = 0.f, ss1 = 0.f;
#pragma unroll
    for (int q = 0; q < 4; q++) {
        f0[q] = src0[lane + 32 * q];
        f1[q] = src1[lane + 32 * q];
        ss0 += f0[q].x * f0[q].x + f0[q].y * f0[q].y + f0[q].z * f0[q].z + f0[q].w * f0[q].w;
        ss1 += f1[q].x * f1[q].x + f1[q].y * f1[q].y + f1[q].z * f1[q].z + f1[q].w * f1[q].w;
    }
#pragma unroll
    for (int o = 16; o; o >>= 1) {
        ss0 += __shfl_xor_sync(0xffffffffu, ss0, o);
        ss1 += __shfl_xor_sync(0xffffffffu, ss1, o);
    }
    float sc0 = 1.0f / fmaxf(sqrtf(ss0), 1e-8f);
    float sc1 = 1.0f / fmaxf(sqrtf(ss1), 1e-8f);
    if (lane == 0) {
        g_Z[b] = 0.f;
        g_Z[BATCH + b] = 0.f;
        atomicAdd(&g_cnt[cls], 1);
    }
    uint2* d0 = reinterpret_cast<uint2*>(g_A + (size_t)b * DIM);
    uint2* d1 = reinterpret_cast<uint2*>(g_A + (size_t)(BATCH + b) * DIM);
    uint32_t* e0 = reinterpret_cast<uint32_t*>(g_A8 + (size_t)b * DIM);
    uint32_t* e1 = reinterpret_cast<uint32_t*>(g_A8 + (size_t)(BATCH + b) * DIM);
    float4* srow = reinterpret_cast<float4*>(stage[warp]);
#pragma unroll
    for (int q = 0; q < 4; q++) {
        float x0 = f0[q].x * sc0, y0 = f0[q].y * sc0, z0 = f0[q].z * sc0, w0 = f0[q].w * sc0;
        float x1 = f1[q].x * sc1, y1 = f1[q].y * sc1, z1 = f1[q].z * sc1, w1 = f1[q].w * sc1;
        __nv_bfloat162 p00 = __floats2bfloat162_rn(x0, y0);
        __nv_bfloat162 p01 = __floats2bfloat162_rn(z0, w0);
        __nv_bfloat162 p10 = __floats2bfloat162_rn(x1, y1);
        __nv_bfloat162 p11 = __floats2bfloat162_rn(z1, w1);
        uint2 pk0, pk1;
        pk0.x = *reinterpret_cast<uint32_t*>(&p00);
        pk0.y = *reinterpret_cast<uint32_t*>(&p01);
        pk1.x = *reinterpret_cast<uint32_t*>(&p10);
        pk1.y = *reinterpret_cast<uint32_t*>(&p11);
        d0[lane + 32 * q] = pk0;
        d1[lane + 32 * q] = pk1;
        __nv_fp8x2_storage_t l0 = __nv_cvt_float2_to_fp8x2(make_float2(x0, y0), __NV_SATFINITE, __NV_E4M3);
        __nv_fp8x2_storage_t h0 = __nv_cvt_float2_to_fp8x2(make_float2(z0, w0), __NV_SATFINITE, __NV_E4M3);
        __nv_fp8x2_storage_t l1 = __nv_cvt_float2_to_fp8x2(make_float2(x1, y1), __NV_SATFINITE, __NV_E4M3);
        __nv_fp8x2_storage_t h1 = __nv_cvt_float2_to_fp8x2(make_float2(z1, w1), __NV_SATFINITE, __NV_E4M3);
        e0[lane + 32 * q] = (uint32_t)l0 | ((uint32_t)h0 << 16);
        e1[lane + 32 * q] = (uint32_t)l1 | ((uint32_t)h1 << 16);
        srow[lane + 32 * q] = make_float4(x0 + x1, y0 + y1, z0 + z1, w0 + w1);
    }
    asm volatile("fence.proxy.async.shared::cta;" ::: "memory");
    __syncwarp();
    if (lane == 0) {
        bulk_red_add_f32(g_Ssum + (size_t)cls * DIM, smem_u32(stage[warp]), DIM * 4);
        bulk_commit();
        bulk_wait0();
    }
}

// ------------------------- kernel 2: fp8 GEMM upper triangle, flat 148-CTA schedule (R13, verified) -------------------------
__global__ void __launch_bounds__(512, 1) supcon_main() {
    extern __shared__ char smem[];
    const int t = threadIdx.x, lane = t & 31, wid = t >> 5;
    const int warp_m = wid >> 2, warp_n = wid & 3;      // 4 x 4 warps, 32x32 tiles
    const int g0 = (NTILES_TOTAL * blockIdx.x) / NCTA;
    const int g1 = (NTILES_TOTAL * (blockIdx.x + 1)) / NCTA;
    const uint32_t sbase = smem_u32(smem);
    const uint32_t mb = sbase + OFF_MBAR;
    float* red = reinterpret_cast<float*>(smem + OFF_RED);   // [4][128]

    if (t == 0) { mbar_init(mb, 1); mbar_init(mb + 8, 1); }

    int ib0, c0;
    decode_tile(g0, ib0, c0);

    // load A tile for first iblk
    for (int f = t; f < 4096; f += 512) {
        int row = f >> 5, seg = f & 31;
        uint4 v = *reinterpret_cast<const uint4*>(g_A8 + (size_t)(ib0 * 128 + row) * DIM + seg * 16);
        *reinterpret_cast<uint4*>(smem + OFF_A + row * A_STRIDE + seg * 16) = v;
    }
    __syncthreads();   // A visible + mbars initialized

    // prologue: bulk-copy B tile of g0 into buf 0
    {
        const int jb = (ib0 + c0) & 63;
        if (t == 0) mbar_expect(mb, 128 * 512);
        if (t < 128)
            bulk_cp(sbase + OFF_B + t * A_STRIDE, g_A8 + (size_t)jb * (128 * DIM) + t * 512, 512, mb);
    }

    const uint32_t abase = sbase + OFF_A + (warp_m * 32 + (lane & 15)) * A_STRIDE + (lane >> 4) * 16;
    const uint32_t bb_lane = (((lane & 7) + ((lane >> 4) & 1) * 8) + warp_n * 32) * A_STRIDE + ((lane >> 3) & 1) * 16;

    float acc[2][4][4];
#pragma unroll
    for (int m = 0; m < 2; m++)
#pragma unroll
        for (int n = 0; n < 4; n++)
#pragma unroll
            for (int r = 0; r < 4; r++) acc[m][n][r] = 0.f;
    float z[4] = {0.f, 0.f, 0.f, 0.f};
    int cur_ib = ib0;

    for (int g = g0; g < g1; g++) {
        const int jl = g - g0;
        const int buf = jl & 1;
        int ib, c;
        decode_tile(g, ib, c);
        __syncthreads();                 // all warps done with buf^1 (tile g-1) and with old A
        if (g + 1 < g1) {
            int ibn, cn;
            decode_tile(g + 1, ibn, cn);
            const int jb = (ibn + cn) & 63;
            const uint32_t mbn = mb + 8 * (buf ^ 1);
            if (t == 0) mbar_expect(mbn, 128 * 512);
            if (t < 128)
                bulk_cp(sbase + OFF_B + (buf ^ 1) * TILE_BYTES + t * A_STRIDE,
                        g_A8 + (size_t)jb * (128 * DIM) + t * 512, 512, mbn);
        }
        if (ib != cur_ib) {
            // flush row sums for cur_ib
#pragma unroll
            for (int q = 0; q < 4; q++) {
                z[q] += __shfl_xor_sync(0xffffffffu, z[q], 1);
                z[q] += __shfl_xor_sync(0xffffffffu, z[q], 2);
            }
            if ((lane & 3) == 0) {
                int g4 = lane >> 2;
#pragma unroll
                for (int m = 0; m < 2; m++)
#pragma unroll
                    for (int h = 0; h < 2; h++)
                        red[warp_n * 128 + warp_m * 32 + m * 16 + h * 8 + g4] = z[2 * m + h];
            }
            __syncthreads();
            if (t < 128)
                atomicAdd(&g_Z[cur_ib * 128 + t],
                          (red[t] + red[128 + t] + red[256 + t] + red[384 + t]) * ESCALE);
            z[0] = z[1] = z[2] = z[3] = 0.f;
            // reload A for new iblk
            for (int f = t; f < 4096; f += 512) {
                int row = f >> 5, seg = f & 31;
                uint4 v = *reinterpret_cast<const uint4*>(g_A8 + (size_t)(ib * 128 + row) * DIM + seg * 16);
                *reinterpret_cast<uint4*>(smem + OFF_A + row * A_STRIDE + seg * 16) = v;
            }
            cur_ib = ib;
            __syncthreads();
        }
        mbar_wait(mb + 8 * buf, (jl >> 1) & 1);

        const uint32_t bb = sbase + OFF_B + buf * TILE_BYTES + bb_lane;
#pragma unroll
        for (int ks = 0; ks < 16; ks++) {
            const int koff = ks * 32;
            uint32_t a[2][4];
            ldm4(a[0], abase + koff);
            ldm4(a[1], abase + 16 * A_STRIDE + koff);
            uint32_t b[4][2];
#pragma unroll
            for (int p = 0; p < 2; p++) {
                uint32_t r4[4];
                ldm4(r4, bb + p * (16 * A_STRIDE) + koff);
                b[2 * p][0] = r4[0]; b[2 * p][1] = r4[1];
                b[2 * p + 1][0] = r4[2]; b[2 * p + 1][1] = r4[3];
            }
#pragma unroll
            for (int m = 0; m < 2; m++)
#pragma unroll
                for (int n = 0; n < 4; n++) qmma(acc[m][n], a[m], b[n]);
        }

        // ---- epilogue: f16x2 exp, row sums + REDG column sums ----
        {
            const int jblk = (ib + c) & 63;
            const bool dg = (c == 0);
            uint32_t zh[4] = {0, 0, 0, 0};
            uint32_t csh[4] = {0, 0, 0, 0};
#pragma unroll
            for (int m = 0; m < 2; m++)
#pragma unroll
                for (int n = 0; n < 4; n++)
#pragma unroll
                    for (int h = 0; h < 2; h++) {
                        float x0 = acc[m][n][2 * h]     * C_EXP - EBIAS;
                        float x1 = acc[m][n][2 * h + 1] * C_EXP - EBIAS;
                        if (dg) {
                            int rl = warp_m * 32 + m * 16 + h * 8 + (lane >> 2);
                            int cl0 = warp_n * 32 + n * 8 + (lane & 3) * 2;
                            if (rl == cl0)     x0 = -60.f;
                            if (rl == cl0 + 1) x1 = -60.f;
                        }
                        uint32_t e2 = ex2_h2(pack_h2(x0, x1));
                        zh[2 * m + h] = hadd2(zh[2 * m + h], e2);
                        csh[n] = hadd2(csh[n], e2);
                        acc[m][n][2 * h] = 0.f; acc[m][n][2 * h + 1] = 0.f;
                    }
#pragma unroll
            for (int q = 0; q < 4; q++) {
                float2 f = h2_to_f2(zh[q]);
                z[q] += f.x + f.y;
            }
            if (!dg) {
#pragma unroll
                for (int n = 0; n < 4; n++) {
                    uint32_t v = csh[n];
                    v = hadd2(v, __shfl_xor_sync(0xffffffffu, v, 4));
                    v = hadd2(v, __shfl_xor_sync(0xffffffffu, v, 8));
                    v = hadd2(v, __shfl_xor_sync(0xffffffffu, v, 16));
                    csh[n] = v;
                }
                if (lane < 4) {
                    float* zj = &g_Z[jblk * 128 + warp_n * 32 + lane * 2];
#pragma unroll
                    for (int n = 0; n < 4; n++) {
                        float2 f = h2_to_f2(csh[n]);
                        atomicAdd(&zj[n * 8 + 0], f.x * ESCALE);
                        atomicAdd(&zj[n * 8 + 1], f.y * ESCALE);
                    }
                }
            }
        }
    }

    // final flush of row sums for cur_ib
#pragma unroll
    for (int q = 0; q < 4; q++) {
        z[q] += __shfl_xor_sync(0xffffffffu, z[q], 1);
        z[q] += __shfl_xor_sync(0xffffffffu, z[q], 2);
    }
    __syncthreads();
    if ((lane & 3) == 0) {
        int g4 = lane >> 2;
#pragma unroll
        for (int m = 0; m < 2; m++)
#pragma unroll
            for (int h = 0; h < 2; h++)
                red[warp_n * 128 + warp_m * 32 + m * 16 + h * 8 + g4] = z[2 * m + h];
    }
    __syncthreads();
    if (t < 128)
        atomicAdd(&g_Z[cur_ib * 128 + t],
                  (red[t] + red[128 + t] + red[256 + t] + red[384 + t]) * ESCALE);
}

// ------------------------- kernel 3: per-sample loss (both views per warp) + last-block final write -------------------------
__global__ void finalize1(const int* __restrict__ labels, float* __restrict__ out) {
    __shared__ float wsum[8];
    const int t = threadIdx.x, lane = t & 31, wid = t >> 5;
    const int b = blockIdx.x * 8 + wid;           // sample 0..4095
    const int cls = labels[b];
    const uint2* a0 = reinterpret_cast<const uint2*>(g_A) + (size_t)b * 128;
    const uint2* a1 = reinterpret_cast<const uint2*>(g_A) + (size_t)(BATCH + b) * 128;
    const float4* srow = reinterpret_cast<const float4*>(g_Ssum) + (size_t)cls * 128;
    float dot0 = 0.f, self0 = 0.f, dot1 = 0.f, self1 = 0.f;
#pragma unroll
    for (int q = 0; q < 4; q++) {
        uint2 u0 = a0[lane + 32 * q];
        uint2 u1 = a1[lane + 32 * q];
        float4 s = srow[lane + 32 * q];
        float2 p00 = __bfloat1622float2(*reinterpret_cast<const __nv_bfloat162*>(&u0.x));
        float2 p01 = __bfloat1622float2(*reinterpret_cast<const __nv_bfloat162*>(&u0.y));
        float2 p10 = __bfloat1622float2(*reinterpret_cast<const __nv_bfloat162*>(&u1.x));
        float2 p11 = __bfloat1622float2(*reinterpret_cast<const __nv_bfloat162*>(&u1.y));
        dot0  += p00.x * s.x + p00.y * s.y + p01.x * s.z + p01.y * s.w;
        self0 += p00.x * p00.x + p00.y * p00.y + p01.x * p01.x + p01.y * p01.y;
        dot1  += p10.x * s.x + p10.y * s.y + p11.x * s.z + p11.y * s.w;
        self1 += p10.x * p10.x + p10.y * p10.y + p11.x * p11.x + p11.y * p11.y;
    }
#pragma unroll
    for (int o = 16; o; o >>= 1) {
        dot0  += __shfl_xor_sync(0xffffffffu, dot0, o);
        self0 += __shfl_xor_sync(0xffffffffu, self0, o);
        dot1  += __shfl_xor_sync(0xffffffffu, dot1, o);
        self1 += __shfl_xor_sync(0xffffffffu, self1, o);
    }
    if (lane == 0) {
        float C = 2.0f * (float)g_cnt[cls] - 1.0f;
        float rC = 1.0f / (C + 1e-8f);
        float l0 = ((dot0 - self0) * INV_T - C * logf(g_Z[b] + 1e-8f)) * rC;
        float l1 = ((dot1 - self1) * INV_T - C * logf(g_Z[BATCH + b] + 1e-8f)) * rC;
        wsum[wid] = l0 + l1;
    }
    __syncthreads();
    if (t == 0) {
        float bs = 0.f;
#pragma unroll
        for (int w = 0; w < 8; w++) bs += wsum[w];
        atomicAdd(&g_sum, bs);
        __threadfence();
        unsigned tk = atomicAdd(&g_done, 1u);
        if (tk == gridDim.x - 1) {
            float s;
            asm volatile("ld.acquire.gpu.f32 %0, [%1];" : "=f"(s) : "l"(&g_sum));
            out[0] = -s / (float)NTOT;
        }
    }
}

// ------------------------- launch -------------------------
extern "C" void kernel_launch(void* const* d_in, const int* in_sizes, int n_in,
                              void* d_out, int out_size) {
    const float* feats = (const float*)d_in[0];
    const int* labels = (const int*)d_in[1];
    (void)in_sizes; (void)n_in; (void)out_size;

    void* p_ssum = nullptr; void* p_cnt = nullptr; void* p_sum = nullptr; void* p_done = nullptr;
    cudaGetSymbolAddress(&p_ssum, g_Ssum);
    cudaGetSymbolAddress(&p_cnt, g_cnt);
    cudaGetSymbolAddress(&p_sum, g_sum);
    cudaGetSymbolAddress(&p_done, g_done);
    cudaMemsetAsync(p_ssum, 0, (size_t)NCLS * DIM * sizeof(float));
    cudaMemsetAsync(p_cnt, 0, NCLS * sizeof(int));
    cudaMemsetAsync(p_sum, 0, sizeof(float));
    cudaMemsetAsync(p_done, 0, sizeof(unsigned));

    cudaFuncSetAttribute(supcon_main, cudaFuncAttributeMaxDynamicSharedMemorySize, SMEM_TOTAL);

    norm_kernel<<<BATCH / 8, 256>>>(feats, labels);
    supcon_main<<<NCTA, 512, SMEM_TOTAL>>>();
    finalize1<<<BATCH / 8, 256>>>(labels, (float*)d_out);
}